// round 17
// baseline (speedup 1.0000x reference)
#include <cuda_runtime.h>
#include <cuda_bf16.h>
#include <cstdint>

// dense_image_warp: out[b,y,x,c] = bilinear(image, (y,x) - flow[b,y,x])
// B=8, H=256, W=256, C=64 (fp32).
// One thread per float4 (4 channels) at one (y,x), 8 batches = 8 iterations.
// Two-stage software pipeline built from ASM VOLATILE gathers (ptxas cannot
// sink/reorder them): batch b+2's 4 corner loads are issued right after batch
// b is consumed, so every warp keeps gathers in flight continuously instead of
// alternating 8-load bursts with memory-idle compute phases.
// Loads carry the L2::evict_last fraction=0.75 policy (R15 best); stores .cs.

struct Stage { float4 tl, tr, bl, br; float ax, ay; };

__device__ __forceinline__ void stcs4(float4* p, float4 v) {
    asm volatile("st.global.cs.v4.f32 [%0], {%1,%2,%3,%4};"
                 :: "l"(p), "f"(v.x), "f"(v.y), "f"(v.z), "f"(v.w) : "memory");
}

// Volatile policy load: pinned in program order w.r.t. other volatile asm.
__device__ __forceinline__ float4 ldg_v(const float4* p, uint64_t pol) {
    float4 v;
    asm volatile("ld.global.nc.L2::cache_hint.v4.f32 {%0,%1,%2,%3}, [%4], %5;"
                 : "=f"(v.x), "=f"(v.y), "=f"(v.z), "=f"(v.w)
                 : "l"(p), "l"(pol));
    return v;
}

__device__ __forceinline__ float4 lerp2d(float4 tl, float4 tr, float4 bl, float4 br,
                                         float ax, float ay) {
    float4 r;
    float top, bot;
    top = fmaf(ax, tr.x - tl.x, tl.x);
    bot = fmaf(ax, br.x - bl.x, bl.x);
    r.x = fmaf(ay, bot - top, top);
    top = fmaf(ax, tr.y - tl.y, tl.y);
    bot = fmaf(ax, br.y - bl.y, bl.y);
    r.y = fmaf(ay, bot - top, top);
    top = fmaf(ax, tr.z - tl.z, tl.z);
    bot = fmaf(ax, br.z - bl.z, bl.z);
    r.z = fmaf(ay, bot - top, top);
    top = fmaf(ax, tr.w - tl.w, tl.w);
    bot = fmaf(ax, br.w - bl.w, bl.w);
    r.w = fmaf(ay, bot - top, top);
    return r;
}

// Compute base + weights and issue the 4 volatile corner gathers for batch b.
__device__ __forceinline__ void issue_batch(const float4* __restrict__ img,
                                            uint64_t pol, int b, int y, int x,
                                            int c4, float2 f, Stage& s) {
    const float qy = (float)y - f.x;
    const float qx = (float)x - f.y;
    const float fy = fminf(fmaxf(floorf(qy), 0.0f), 254.0f);
    const float fx = fminf(fmaxf(floorf(qx), 0.0f), 254.0f);
    s.ay = fminf(fmaxf(qy - fy, 0.0f), 1.0f);
    s.ax = fminf(fmaxf(qx - fx, 0.0f), 1.0f);
    const int base = ((((b << 8) + (int)fy) << 8) + (int)fx) * 16 + c4;
    s.tl = ldg_v(img + base, pol);
    s.tr = ldg_v(img + base + 16, pol);
    s.bl = ldg_v(img + base + 16 * 256, pol);
    s.br = ldg_v(img + base + 16 * 256 + 16, pol);
}

__global__ __launch_bounds__(256) void warp_kernel(
    const float4* __restrict__ img,    // [B,H,W,C] as float4, pixel stride 16
    const float2* __restrict__ flow,   // [B,H,W,2] as float2, one per pixel
    float4* __restrict__ out)
{
    const int tid = blockIdx.x * blockDim.x + threadIdx.x;  // 0..2^20-1
    const int c4 = tid & 15;          // channel group 0..15
    const int p  = tid >> 4;          // (y,x) pixel index 0..65535
    const int x  = p & 255;
    const int y  = p >> 8;

    uint64_t pol;
    asm("createpolicy.fractional.L2::evict_last.b64 %0, 0.75;" : "=l"(pol));

    Stage st[2];

    // Prologue: fill both pipeline stages (batches 0 and 1).
    float2 fa = __ldg(&flow[p]);                 // batch 0
    float2 fb = __ldg(&flow[p + 65536]);         // batch 1
    issue_batch(img, pol, 0, y, x, c4, fa, st[0]);
    fa = __ldg(&flow[p + 2 * 65536]);            // batch 2
    issue_batch(img, pol, 1, y, x, c4, fb, st[1]);
    fb = __ldg(&flow[p + 3 * 65536]);            // batch 3

    #pragma unroll
    for (int b = 0; b < 8; ++b) {
        const int s = b & 1;

        // Consume batch b (loads were issued two iterations ago).
        const float4 r = lerp2d(st[s].tl, st[s].tr, st[s].bl, st[s].br,
                                st[s].ax, st[s].ay);
        stcs4(out + tid + b * 1048576, r);

        // Refill this stage with batch b+2; prefetch flow for batch b+4.
        if (b + 2 < 8) {
            issue_batch(img, pol, b + 2, y, x, c4, (b & 1) ? fb : fa, st[s]);
            if (b + 4 < 8) {
                if (b & 1) fb = __ldg(&flow[p + (b + 4) * 65536]);
                else       fa = __ldg(&flow[p + (b + 4) * 65536]);
            }
        }
    }
}

extern "C" void kernel_launch(void* const* d_in, const int* in_sizes, int n_in,
                              void* d_out, int out_size)
{
    const float4* img  = (const float4*)d_in[0];
    const float2* flow = (const float2*)d_in[1];
    float4* out = (float4*)d_out;

    // 65536 (y,x) pixels * 16 channel-groups = 1048576 threads, 8 batches each
    const int threads = 1 << 20;
    const int block = 256;
    const int grid = threads / block;  // 4096
    warp_kernel<<<grid, block>>>(img, flow, out);
}